// round 7
// baseline (speedup 1.0000x reference)
#include <cuda_runtime.h>

// ConceptGaussians: per-domain gather.
//   labels  : [B=2097152, 8] int32 in [0,64)
//   mean    : [8, 64] f32
//   log_var : [8, 64] f32
// Output: [ means[B,8] | log_vars[B,8] ] f32.
//
// Latency-structure-bound fix vs R5: grid-stride, 4 samples/thread,
// front-batched label loads (MLP=8), table loaded once per (fat) block.

#define TPB   256
#define SPT   4          // samples per thread

__global__ void __launch_bounds__(TPB)
concept_gather_kernel(const int4* __restrict__ lab4,
                      const float* __restrict__ g_mean,
                      const float* __restrict__ g_lv,
                      float4* __restrict__ out_m,
                      float4* __restrict__ out_v,
                      int n)
{
    // Fused (mean, log_var) table: 512 float2 = 4 KiB.
    __shared__ float2 tab[512];
    #pragma unroll
    for (int i = threadIdx.x; i < 512; i += TPB)
        tab[i] = make_float2(g_mean[i], g_lv[i]);
    __syncthreads();

    const int chunk = TPB * SPT;                    // samples per block
    const int base  = blockIdx.x * chunk + threadIdx.x;
    const int stride = gridDim.x * chunk;

    for (int b0 = base; b0 < n; b0 += stride) {
        // ---- phase 1: front-batch all label loads (up to 8 LDG.128 in flight)
        int4 l0[SPT], l1[SPT];
        int   bs[SPT];
        #pragma unroll
        for (int s = 0; s < SPT; s++) {
            int b = b0 + s * TPB;
            bs[s] = b;
            if (b < n) {
                l0[s] = __ldcs(&lab4[2 * b]);
                l1[s] = __ldcs(&lab4[2 * b + 1]);
            }
        }

        // ---- phase 2: shared-table lookups + streaming stores
        #pragma unroll
        for (int s = 0; s < SPT; s++) {
            int b = bs[s];
            if (b >= n) continue;

            float2 t0 = tab[       l0[s].x];
            float2 t1 = tab[ 64 +  l0[s].y];
            float2 t2 = tab[128 +  l0[s].z];
            float2 t3 = tab[192 +  l0[s].w];
            float2 t4 = tab[256 +  l1[s].x];
            float2 t5 = tab[320 +  l1[s].y];
            float2 t6 = tab[384 +  l1[s].z];
            float2 t7 = tab[448 +  l1[s].w];

            __stcs(&out_m[2 * b],     make_float4(t0.x, t1.x, t2.x, t3.x));
            __stcs(&out_m[2 * b + 1], make_float4(t4.x, t5.x, t6.x, t7.x));
            __stcs(&out_v[2 * b],     make_float4(t0.y, t1.y, t2.y, t3.y));
            __stcs(&out_v[2 * b + 1], make_float4(t4.y, t5.y, t6.y, t7.y));
        }
    }
}

extern "C" void kernel_launch(void* const* d_in, const int* in_sizes, int n_in,
                              void* d_out, int out_size)
{
    const int4*  labels = (const int4*)d_in[0];   // [B,8] int32 as 2x int4
    const float* g_mean = (const float*)d_in[1];  // [8,64]
    const float* g_lv   = (const float*)d_in[2];  // [8,64]

    int n = in_sizes[0] / 8;                      // B samples

    float4* out_m = (float4*)d_out;               // means half
    float4* out_v = out_m + (size_t)n * 2;        // log_var half

    int blocks = (n + TPB * SPT - 1) / (TPB * SPT);   // 2048 for B=2M
    concept_gather_kernel<<<blocks, TPB>>>(labels, g_mean, g_lv, out_m, out_v, n);
}

// round 8
// speedup vs baseline: 1.0386x; 1.0386x over previous
#include <cuda_runtime.h>

// ConceptGaussians: per-domain gather.
//   labels  : [B=2097152, 8] int32 in [0,64)
//   mean    : [8, 64] f32;  log_var : [8, 64] f32
// Output: [ means[B,8] | log_vars[B,8] ] f32.
//
// R7: grid-stride (4 iters/thread) with software-pipelined label prefetch.
// Keeps regs low (high occupancy) while holding 4 LDG.128 in flight per
// thread -> ~2x more outstanding reads per SMSP than R5 without the
// front-batch CTA-spread penalty of R6.

#define TPB 256

__global__ void __launch_bounds__(TPB)
concept_gather_kernel(const int4* __restrict__ lab4,
                      const float* __restrict__ g_mean,
                      const float* __restrict__ g_lv,
                      float4* __restrict__ out_m,
                      float4* __restrict__ out_v,
                      int n)
{
    // Fused (mean, log_var) table: 512 float2 = 4 KiB.
    __shared__ float2 tab[512];
    #pragma unroll
    for (int i = threadIdx.x; i < 512; i += TPB)
        tab[i] = make_float2(g_mean[i], g_lv[i]);
    __syncthreads();

    const int stride = gridDim.x * TPB;
    int i = blockIdx.x * TPB + threadIdx.x;
    if (i >= n) return;

    // Prime the pipeline.
    int4 c0 = __ldcs(&lab4[2 * i]);
    int4 c1 = __ldcs(&lab4[2 * i + 1]);

    for (;;) {
        // Prefetch next iteration's labels (in flight during this body).
        const int j = i + stride;
        const bool more = (j < n);
        int4 p0, p1;
        if (more) {
            p0 = __ldcs(&lab4[2 * j]);
            p1 = __ldcs(&lab4[2 * j + 1]);
        }

        // Shared-table lookups (domain d at tab[d*64 + idx]).
        float2 t0 = tab[       c0.x];
        float2 t1 = tab[ 64 +  c0.y];
        float2 t2 = tab[128 +  c0.z];
        float2 t3 = tab[192 +  c0.w];
        float2 t4 = tab[256 +  c1.x];
        float2 t5 = tab[320 +  c1.y];
        float2 t6 = tab[384 +  c1.z];
        float2 t7 = tab[448 +  c1.w];

        // Coalesced streaming STG.128 into the two output halves.
        __stcs(&out_m[2 * i],     make_float4(t0.x, t1.x, t2.x, t3.x));
        __stcs(&out_m[2 * i + 1], make_float4(t4.x, t5.x, t6.x, t7.x));
        __stcs(&out_v[2 * i],     make_float4(t0.y, t1.y, t2.y, t3.y));
        __stcs(&out_v[2 * i + 1], make_float4(t4.y, t5.y, t6.y, t7.y));

        if (!more) break;
        i = j; c0 = p0; c1 = p1;
    }
}

extern "C" void kernel_launch(void* const* d_in, const int* in_sizes, int n_in,
                              void* d_out, int out_size)
{
    const int4*  labels = (const int4*)d_in[0];   // [B,8] int32 as 2x int4
    const float* g_mean = (const float*)d_in[1];  // [8,64]
    const float* g_lv   = (const float*)d_in[2];  // [8,64]

    int n = in_sizes[0] / 8;                      // B samples

    float4* out_m = (float4*)d_out;               // means half
    float4* out_v = out_m + (size_t)n * 2;        // log_var half

    // 4 samples per thread: B=2M / (2048*256) = 4 exact iterations.
    int iters  = 4;
    int blocks = (n + TPB * iters - 1) / (TPB * iters);
    concept_gather_kernel<<<blocks, TPB>>>(labels, g_mean, g_lv, out_m, out_v, n);
}